// round 15
// baseline (speedup 1.0000x reference)
#include <cuda_runtime.h>
#include <cstdint>

// ---------------- problem constants ----------------
#define B_   32
#define H_   168
#define N_   512
#define F_   8
#define P_   24
#define KIN_ (N_ * F_)   // 4096
#define G4N_ (4 * N_)    // 2048
#define MR_  (B_ * H_)   // 5376
#define RGRID 128        // recurrence grid (all co-resident; 128 <= 148 SMs)
#define HS_  516         // hsh row stride (conflict-free A-frag loads)
#define WS_  24          // W smem row stride (conflict-free B-frag loads)
#define PS_  36          // psum b-stride (conflict-free partial STS/LDS)

typedef unsigned long long ull;

// ---------------- device scratch (no runtime allocation allowed) ----------------
__device__ float d_xr[(size_t)MR_ * N_];        // 11 MB
__device__ float d_xk[(size_t)MR_ * G4N_];      // 44 MB (includes lstm_b)
__device__ float d_wdec[(size_t)N_ * G4N_];     // 4 MB  (lstm_k + lstm_rk)
__device__ float d_cw[(size_t)KIN_ * N_];       // conv_w pre-tf32 (8 MB)
__device__ float d_lk[(size_t)N_ * G4N_];       // lstm_k pre-tf32 (4 MB)
__device__ float d_dw[(size_t)N_ * N_];         // dense_w pre-tf32 (1 MB)
__device__ float d_h[2][B_ * N_];               // h[b][n], double buffered
__device__ float d_preds[(size_t)B_ * P_ * N_]; // 1.5 MB
__device__ unsigned g_flags[RGRID * 32];        // per-block monotonic publish flags

// ---------------- tf32 helpers ----------------
__device__ __forceinline__ unsigned f2tf(float x) {
    unsigned r;
    asm("cvt.rna.tf32.f32 %0, %1;" : "=r"(r) : "f"(x));
    return r;
}

__device__ __forceinline__ void mma_tf32(float* c, const unsigned* a,
                                         unsigned b0, unsigned b1) {
    asm volatile(
        "mma.sync.aligned.m16n8k8.row.col.f32.tf32.tf32.f32 "
        "{%0,%1,%2,%3},{%4,%5,%6,%7},{%8,%9},{%0,%1,%2,%3};"
        : "+f"(c[0]), "+f"(c[1]), "+f"(c[2]), "+f"(c[3])
        : "r"(a[0]), "r"(a[1]), "r"(a[2]), "r"(a[3]), "r"(b0), "r"(b1));
}

__device__ __forceinline__ unsigned sm_u32(const void* p) {
    return (unsigned)__cvta_generic_to_shared(p);
}

// ======================================================================
// prep: convert weights to tf32 (bit patterns in float) + wdec = lk + rk
// ======================================================================
__global__ void prep(const float* __restrict__ cw, const float* __restrict__ lk,
                     const float* __restrict__ rk, const float* __restrict__ dw)
{
    int i = blockIdx.x * blockDim.x + threadIdx.x;
    if (i < KIN_ * N_) d_cw[i] = __uint_as_float(f2tf(cw[i]));
    if (i < N_ * G4N_) {
        d_lk[i]   = __uint_as_float(f2tf(lk[i]));
        d_wdec[i] = lk[i] + rk[i];
    }
    if (i < N_ * N_) d_dw[i] = __uint_as_float(f2tf(dw[i]));
}

// ======================================================================
// C[M,N] = A[M,K] @ B[K,N] + bias[N], tf32 mma, cp.async 3-stage pipeline.
// Block tile 128x128 (2 blocks/SM), 8 warps (4x2), warp tile 32x64.
// A raw fp32 (cvt.rna after frag LDS), B pre-converted tf32 bits.
// ======================================================================
#define BM 128
#define BN 128
#define BKt 32
#define NSTG 3
#define ASZ (BM * (BKt + 4))   // 4608 floats / stage
#define BSZ (BKt * (BN + 4))   // 4224 floats / stage

__global__ __launch_bounds__(256, 2) void gemm_pipe(
    const float* __restrict__ A, const float* __restrict__ Bt,
    const float* __restrict__ bias, float* __restrict__ C,
    int M, int N, int K)
{
    extern __shared__ float smg[];
    float* As = smg;                 // NSTG * ASZ
    float* Bs = smg + NSTG * ASZ;    // NSTG * BSZ

    const int tid  = threadIdx.x;
    const int lane = tid & 31;
    const int warp = tid >> 5;
    const int wm = warp & 3;    // 0..3 (M)
    const int wn = warp >> 2;   // 0..1 (N)
    const int bm = blockIdx.y, bn = blockIdx.x;
    const int g  = lane >> 2;
    const int tg = lane & 3;

    const float* Ag = A + (size_t)bm * BM * K;
    const float* Bg = Bt + (size_t)bn * BN;

    int arow[4], akc[4], brow[4], bnc[4];
#pragma unroll
    for (int i = 0; i < 4; i++) {
        int f4 = tid + i * 256;
        arow[i] = f4 >> 3;           // 8 f4 per A row
        akc[i]  = (f4 & 7) << 2;
        brow[i] = f4 >> 5;           // 32 f4 per B row
        bnc[i]  = (f4 & 31) << 2;
    }

    float acc[2][8][4];
#pragma unroll
    for (int i = 0; i < 2; i++)
#pragma unroll
        for (int j = 0; j < 8; j++)
#pragma unroll
            for (int r = 0; r < 4; r++) acc[i][j][r] = 0.f;

    const int T = K / BKt;

    auto issue = [&](int t, int buf) {
#pragma unroll
        for (int i = 0; i < 4; i++) {
            unsigned dst = sm_u32(&As[buf * ASZ + arow[i] * (BKt + 4) + akc[i]]);
            const float* src = Ag + (size_t)arow[i] * K + t * BKt + akc[i];
            asm volatile("cp.async.cg.shared.global [%0], [%1], 16;"
                         :: "r"(dst), "l"(src));
        }
#pragma unroll
        for (int i = 0; i < 4; i++) {
            unsigned dst = sm_u32(&Bs[buf * BSZ + brow[i] * (BN + 4) + bnc[i]]);
            const float* src = Bg + (size_t)(t * BKt + brow[i]) * N + bnc[i];
            asm volatile("cp.async.cg.shared.global [%0], [%1], 16;"
                         :: "r"(dst), "l"(src));
        }
        asm volatile("cp.async.commit_group;");
    };

    issue(0, 0);
    issue(1, 1);

    for (int t = 0; t < T; t++) {
        asm volatile("cp.async.wait_group 1;");
        __syncthreads();

        if (t + 2 < T) issue(t + 2, (t + 2) % NSTG);
        else asm volatile("cp.async.commit_group;");

        const int buf = t % NSTG;
        const float* Ab = As + buf * ASZ;
        const float* Bb = Bs + buf * BSZ;

#pragma unroll
        for (int ks = 0; ks < 4; ks++) {
            const int k0 = ks * 8;
            unsigned a[2][4], b[8][2];
#pragma unroll
            for (int mi = 0; mi < 2; mi++) {
                int m0 = wm * 32 + mi * 16;
                a[mi][0] = f2tf(Ab[(m0 + g    ) * (BKt + 4) + k0 + tg    ]);
                a[mi][1] = f2tf(Ab[(m0 + g + 8) * (BKt + 4) + k0 + tg    ]);
                a[mi][2] = f2tf(Ab[(m0 + g    ) * (BKt + 4) + k0 + tg + 4]);
                a[mi][3] = f2tf(Ab[(m0 + g + 8) * (BKt + 4) + k0 + tg + 4]);
            }
#pragma unroll
            for (int ni = 0; ni < 8; ni++) {
                int n0 = wn * 64 + ni * 8;
                b[ni][0] = __float_as_uint(Bb[(k0 + tg    ) * (BN + 4) + n0 + g]);
                b[ni][1] = __float_as_uint(Bb[(k0 + tg + 4) * (BN + 4) + n0 + g]);
            }
#pragma unroll
            for (int mi = 0; mi < 2; mi++)
#pragma unroll
                for (int ni = 0; ni < 8; ni++)
                    mma_tf32(acc[mi][ni], a[mi], b[ni][0], b[ni][1]);
        }
        __syncthreads();
    }

#pragma unroll
    for (int mi = 0; mi < 2; mi++) {
        int r0 = bm * BM + wm * 32 + mi * 16 + g;
#pragma unroll
        for (int ni = 0; ni < 8; ni++) {
            int c0 = bn * BN + wn * 64 + ni * 8 + tg * 2;
            float b0 = bias[c0], b1 = bias[c0 + 1];
            *(float2*)(C + (size_t)r0 * N + c0) =
                make_float2(acc[mi][ni][0] + b0, acc[mi][ni][1] + b1);
            *(float2*)(C + (size_t)(r0 + 8) * N + c0) =
                make_float2(acc[mi][ni][2] + b0, acc[mi][ni][3] + b1);
        }
    }
}

// ======================================================================
// Persistent recurrence kernel — UNCHANGED from R13/R14 (passing, 847 us).
// ======================================================================
__device__ __forceinline__ float sigf(float x) { return 1.f / (1.f + expf(-x)); }

__device__ __forceinline__ void stage_w(const float* __restrict__ W, int nc0,
                                        unsigned* wHi, unsigned* wLo, int tid)
{
    for (int i = tid; i < 2048; i += 512) {
        int k = i >> 2, gate = i & 3;
        float4 w = *(const float4*)(W + (size_t)k * G4N_ + gate * 512 + nc0);
        unsigned h0 = f2tf(w.x), h1 = f2tf(w.y), h2 = f2tf(w.z), h3 = f2tf(w.w);
        unsigned l0 = __float_as_uint(w.x - __uint_as_float(h0));
        unsigned l1 = __float_as_uint(w.y - __uint_as_float(h1));
        unsigned l2 = __float_as_uint(w.z - __uint_as_float(h2));
        unsigned l3 = __float_as_uint(w.w - __uint_as_float(h3));
        *(uint4*)&wHi[k * WS_ + gate * 4] = make_uint4(h0, h1, h2, h3);
        *(uint4*)&wLo[k * WS_ + gate * 4] = make_uint4(l0, l1, l2, l3);
    }
}

__global__ __launch_bounds__(512, 1) void recurrence(
    const float* __restrict__ Wenc,   // lstm_rk [512][2048]
    const float* __restrict__ Wdec,   // [512][2048]
    const float* __restrict__ xk,     // [B*H][2048] (bias folded in)
    const float* __restrict__ lb,     // lstm_b [2048]
    float* __restrict__ preds)        // [B][P][N]
{
    extern __shared__ float sm[];
    unsigned* wHi = (unsigned*)sm;            // 12288 u32
    unsigned* wLo = (unsigned*)(sm + 12288);  // 12288 u32
    float* hsh    = sm + 24576;               // 32 x 516 = 16512 floats
    float* psumB  = sm + 41088;               // 2 x 4608 floats (step parity)

    const int tid  = threadIdx.x;
    const int lane = tid & 31;
    const int warp = tid >> 5;
    const int g    = lane >> 2;
    const int tg   = lane & 3;
    const int kg   = warp & 7;     // k-split group
    const int mi   = warp >> 3;    // row half
    const int m0   = mi * 16;
    const int nc0  = blockIdx.x * 4;

    const unsigned base = g_flags[blockIdx.x * 32];

    stage_w(Wenc, nc0, wHi, wLo, tid);

    const int b  = tid & 31;
    const int cu = tid >> 5;
    float lbr[4], cst = 0.f, pf[4];
    if (tid < 128) {
        d_h[0][(size_t)b * N_ + nc0 + cu] = 0.f;
#pragma unroll
        for (int q = 0; q < 4; q++) lbr[q] = lb[q * 512 + nc0 + cu];
        const float* xp = xk + ((size_t)b * H_) * G4N_ + nc0 + cu;
        pf[0] = __ldg(xp);
        pf[1] = __ldg(xp + 512);
        pf[2] = __ldg(xp + 1024);
        pf[3] = __ldg(xp + 1536);
    }
    __syncthreads();
    if (tid == 0)
        asm volatile("st.release.gpu.global.u32 [%0], %1;"
                     :: "l"(&g_flags[blockIdx.x * 32]), "r"(base + 1u) : "memory");

    const int jj = kg * 16 + (lane & 15);
    const unsigned* flagp = &g_flags[jj * 32];
    const int half = lane >> 4;
    const int r0s  = m0 + half * 8;
    const int scol = kg * 64 + (lane & 15) * 4;

    for (int s = 0; s < H_ + P_; s++) {
        if (s == H_) {
            stage_w(Wdec, nc0, wHi, wLo, tid);
            __syncthreads();
        }

        float pfn[4];
        if (tid < 128) {
            if (s + 1 < H_) {
                const float* xp = xk + ((size_t)b * H_ + (s + 1)) * G4N_ + nc0 + cu;
                pfn[0] = __ldg(xp);
                pfn[1] = __ldg(xp + 512);
                pfn[2] = __ldg(xp + 1024);
                pfn[3] = __ldg(xp + 1536);
            } else {
                pfn[0] = lbr[0]; pfn[1] = lbr[1]; pfn[2] = lbr[2]; pfn[3] = lbr[3];
            }
        }

        {
            const unsigned tgt = base + 1u + (unsigned)s;
            unsigned v;
            do {
                asm volatile("ld.acquire.gpu.global.u32 %0, [%1];"
                             : "=r"(v) : "l"(flagp) : "memory");
            } while ((int)(v - tgt) < 0);
        }
        {
            const float4* hb = (const float4*)d_h[s & 1];
            float4 hv[8];
#pragma unroll
            for (int r = 0; r < 8; r++)
                hv[r] = __ldcg(hb + (size_t)(r0s + r) * 128 + jj);
#pragma unroll
            for (int r = 0; r < 8; r++)
                *(float4*)&hsh[(r0s + r) * HS_ + scol] = hv[r];
        }
        __syncwarp();

        float ac0[2][4] = {{0.f,0.f,0.f,0.f},{0.f,0.f,0.f,0.f}};
        float ac1[2][4] = {{0.f,0.f,0.f,0.f},{0.f,0.f,0.f,0.f}};
#pragma unroll
        for (int f = 0; f < 8; f++) {
            const int k0 = kg * 64 + f * 8;
            const int c = f & 1;
            float a0 = hsh[(m0 + g    ) * HS_ + k0 + tg    ];
            float a1 = hsh[(m0 + g + 8) * HS_ + k0 + tg    ];
            float a2 = hsh[(m0 + g    ) * HS_ + k0 + tg + 4];
            float a3 = hsh[(m0 + g + 8) * HS_ + k0 + tg + 4];
            unsigned ahi[4], alo[4];
            ahi[0] = f2tf(a0); alo[0] = __float_as_uint(a0 - __uint_as_float(ahi[0]));
            ahi[1] = f2tf(a1); alo[1] = __float_as_uint(a1 - __uint_as_float(ahi[1]));
            ahi[2] = f2tf(a2); alo[2] = __float_as_uint(a2 - __uint_as_float(ahi[2]));
            ahi[3] = f2tf(a3); alo[3] = __float_as_uint(a3 - __uint_as_float(ahi[3]));
            unsigned bh0 = wHi[(k0 + tg    ) * WS_ + g];
            unsigned bh1 = wHi[(k0 + tg + 4) * WS_ + g];
            unsigned bh2 = wHi[(k0 + tg    ) * WS_ + 8 + g];
            unsigned bh3 = wHi[(k0 + tg + 4) * WS_ + 8 + g];
            unsigned bl0 = wLo[(k0 + tg    ) * WS_ + g];
            unsigned bl1 = wLo[(k0 + tg + 4) * WS_ + g];
            unsigned bl2 = wLo[(k0 + tg    ) * WS_ + 8 + g];
            unsigned bl3 = wLo[(k0 + tg + 4) * WS_ + 8 + g];
            mma_tf32(ac0[c], ahi, bh0, bh1);
            mma_tf32(ac0[c], alo, bh0, bh1);
            mma_tf32(ac0[c], ahi, bl0, bl1);
            mma_tf32(ac1[c], ahi, bh2, bh3);
            mma_tf32(ac1[c], alo, bh2, bh3);
            mma_tf32(ac1[c], ahi, bl2, bl3);
        }
        {
            float* psum = psumB + (s & 1) * 4608;
            const int c0 = tg * 2, r0 = m0 + g;
            psum[(kg * 16 + c0        ) * PS_ + r0    ] = ac0[0][0] + ac0[1][0];
            psum[(kg * 16 + c0 + 1    ) * PS_ + r0    ] = ac0[0][1] + ac0[1][1];
            psum[(kg * 16 + c0        ) * PS_ + r0 + 8] = ac0[0][2] + ac0[1][2];
            psum[(kg * 16 + c0 + 1    ) * PS_ + r0 + 8] = ac0[0][3] + ac0[1][3];
            psum[(kg * 16 + 8 + c0    ) * PS_ + r0    ] = ac1[0][0] + ac1[1][0];
            psum[(kg * 16 + 8 + c0 + 1) * PS_ + r0    ] = ac1[0][1] + ac1[1][1];
            psum[(kg * 16 + 8 + c0    ) * PS_ + r0 + 8] = ac1[0][2] + ac1[1][2];
            psum[(kg * 16 + 8 + c0 + 1) * PS_ + r0 + 8] = ac1[0][3] + ac1[1][3];
        }
        __syncthreads();

        if (tid < 128) {
            const float* psum = psumB + (s & 1) * 4608;
            float z[4];
#pragma unroll
            for (int q = 0; q < 4; q++) {
                const int n = q * 4 + cu;
                float accv = pf[q];
#pragma unroll
                for (int kk = 0; kk < 8; kk++)
                    accv += psum[(kk * 16 + n) * PS_ + b];
                z[q] = accv;
            }
            float ii = sigf(z[0]), ff = sigf(z[1]);
            float gg = tanhf(z[2]), oo = sigf(z[3]);
            cst = ff * cst + ii * gg;
            float hn = oo * tanhf(cst);
            d_h[(s + 1) & 1][(size_t)b * N_ + nc0 + cu] = hn;

            asm volatile("bar.sync 1, 128;" ::: "memory");
            if (tid == 0)
                asm volatile("st.release.gpu.global.u32 [%0], %1;"
                             :: "l"(&g_flags[blockIdx.x * 32]),
                                "r"(base + 2u + (unsigned)s) : "memory");

            if (s >= H_)
                preds[((size_t)b * P_ + (s - H_)) * N_ + nc0 + cu] = hn;

            pf[0] = pfn[0]; pf[1] = pfn[1]; pf[2] = pfn[2]; pf[3] = pfn[3];
        }
    }
}

// ======================================================================
// launch
// ======================================================================
extern "C" void kernel_launch(void* const* d_in, const int* in_sizes, int n_in,
                              void* d_out, int out_size)
{
    const float* x       = (const float*)d_in[0];
    const float* conv_w  = (const float*)d_in[1];
    const float* conv_b  = (const float*)d_in[2];
    const float* lstm_k  = (const float*)d_in[3];
    const float* lstm_rk = (const float*)d_in[4];
    const float* lstm_b  = (const float*)d_in[5];
    const float* dense_w = (const float*)d_in[6];
    const float* dense_b = (const float*)d_in[7];
    float* out = (float*)d_out;

    float *xr, *xk, *wdec, *preds, *cw, *lk, *dw;
    cudaGetSymbolAddress((void**)&xr,    d_xr);
    cudaGetSymbolAddress((void**)&xk,    d_xk);
    cudaGetSymbolAddress((void**)&wdec,  d_wdec);
    cudaGetSymbolAddress((void**)&preds, d_preds);
    cudaGetSymbolAddress((void**)&cw,    d_cw);
    cudaGetSymbolAddress((void**)&lk,    d_lk);
    cudaGetSymbolAddress((void**)&dw,    d_dw);

    const int GSMEM = NSTG * (ASZ + BSZ) * 4;  // 105984 B (2 blocks/SM)
    cudaFuncSetAttribute(gemm_pipe, cudaFuncAttributeMaxDynamicSharedMemorySize, GSMEM);
    const int RSMEM = (12288 + 12288 + 16512 + 2 * 4608) * 4;  // 201216 B
    cudaFuncSetAttribute(recurrence, cudaFuncAttributeMaxDynamicSharedMemorySize, RSMEM);

    // 0) weight prep: tf32 conversions + wdec = lstm_k + lstm_rk
    prep<<<(KIN_ * N_ + 255) / 256, 256>>>(conv_w, lstm_k, lstm_rk, dense_w);

    // 1) xr = reshape(x) @ conv_w + conv_b     [5376,4096]x[4096,512]
    {
        dim3 grid(N_ / BN, MR_ / BM);            // (4, 42)
        gemm_pipe<<<grid, 256, GSMEM>>>(x, cw, conv_b, xr, MR_, N_, KIN_);
    }
    // 2) xk = xr @ lstm_k + lstm_b             [5376,512]x[512,2048]
    {
        dim3 grid(G4N_ / BN, MR_ / BM);          // (16, 42)
        gemm_pipe<<<grid, 256, GSMEM>>>(xr, lk, lstm_b, xk, MR_, G4N_, N_);
    }
    // 3) encoder (168 steps) + decoder (24 steps), persistent dataflow
    recurrence<<<RGRID, 512, RSMEM>>>(lstm_rk, wdec, xk, lstm_b, preds);
    // 4) out = preds @ dense_w + dense_b       [768,512]x[512,512]
    {
        dim3 grid(N_ / BN, (B_ * P_) / BM);      // (4, 6)
        gemm_pipe<<<grid, 256, GSMEM>>>(preds, dw, dense_b, out, B_ * P_, N_, N_);
    }
}

// round 16
// speedup vs baseline: 1.1054x; 1.1054x over previous
#include <cuda_runtime.h>
#include <cstdint>

// ---------------- problem constants ----------------
#define B_   32
#define H_   168
#define N_   512
#define F_   8
#define P_   24
#define KIN_ (N_ * F_)   // 4096
#define G4N_ (4 * N_)    // 2048
#define MR_  (B_ * H_)   // 5376
#define RGRID 128        // recurrence grid (all co-resident; 128 <= 148 SMs)
#define HS_  516         // hsh row stride
#define WS2_ 24          // packed-W row stride (conflict-free B-frag LDS)
#define PS_  36          // psum b-stride

typedef unsigned long long ull;

// ---------------- device scratch ----------------
__device__ float d_xr[(size_t)MR_ * N_];
__device__ float d_xk[(size_t)MR_ * G4N_];
__device__ float d_wdec[(size_t)N_ * G4N_];
__device__ float d_cw[(size_t)KIN_ * N_];
__device__ float d_lk[(size_t)N_ * G4N_];
__device__ float d_dw[(size_t)N_ * N_];
__device__ float d_h[2][B_ * N_];
__device__ float d_preds[(size_t)B_ * P_ * N_];
__device__ unsigned g_flags[RGRID * 32];

// ---------------- helpers ----------------
__device__ __forceinline__ unsigned f2tf(float x) {
    unsigned r;
    asm("cvt.rna.tf32.f32 %0, %1;" : "=r"(r) : "f"(x));
    return r;
}

__device__ __forceinline__ void mma_tf32(float* c, const unsigned* a,
                                         unsigned b0, unsigned b1) {
    asm volatile(
        "mma.sync.aligned.m16n8k8.row.col.f32.tf32.tf32.f32 "
        "{%0,%1,%2,%3},{%4,%5,%6,%7},{%8,%9},{%0,%1,%2,%3};"
        : "+f"(c[0]), "+f"(c[1]), "+f"(c[2]), "+f"(c[3])
        : "r"(a[0]), "r"(a[1]), "r"(a[2]), "r"(a[3]), "r"(b0), "r"(b1));
}

__device__ __forceinline__ void mma_bf16(float* c, const unsigned* a,
                                         unsigned b0, unsigned b1) {
    asm volatile(
        "mma.sync.aligned.m16n8k16.row.col.f32.bf16.bf16.f32 "
        "{%0,%1,%2,%3},{%4,%5,%6,%7},{%8,%9},{%0,%1,%2,%3};"
        : "+f"(c[0]), "+f"(c[1]), "+f"(c[2]), "+f"(c[3])
        : "r"(a[0]), "r"(a[1]), "r"(a[2]), "r"(a[3]), "r"(b0), "r"(b1));
}

// pack float2 (even=x, odd=y) -> bf16x2 hi word + bf16x2 lo-residual word
__device__ __forceinline__ void pack_hl(float2 p, unsigned& hi, unsigned& lo) {
    asm("cvt.rn.bf16x2.f32 %0, %1, %2;" : "=r"(hi) : "f"(p.y), "f"(p.x));
    float eh = __uint_as_float(hi << 16);
    float oh = __uint_as_float(hi & 0xFFFF0000u);
    float el = p.x - eh, ol = p.y - oh;
    asm("cvt.rn.bf16x2.f32 %0, %1, %2;" : "=r"(lo) : "f"(ol), "f"(el));
}

__device__ __forceinline__ unsigned sm_u32(const void* p) {
    return (unsigned)__cvta_generic_to_shared(p);
}

// ======================================================================
// prep (unchanged from R14)
// ======================================================================
__global__ void prep(const float* __restrict__ cw, const float* __restrict__ lk,
                     const float* __restrict__ rk, const float* __restrict__ dw)
{
    int i = blockIdx.x * blockDim.x + threadIdx.x;
    if (i < KIN_ * N_) d_cw[i] = __uint_as_float(f2tf(cw[i]));
    if (i < N_ * G4N_) {
        d_lk[i]   = __uint_as_float(f2tf(lk[i]));
        d_wdec[i] = lk[i] + rk[i];
    }
    if (i < N_ * N_) d_dw[i] = __uint_as_float(f2tf(dw[i]));
}

// ======================================================================
// GEMM — exact R14 config (best measured): 128x64 tile, cp.async 3-stage
// ======================================================================
#define BM 128
#define BN 64
#define BKt 32
#define NSTG 3
#define ASZ (BM * (BKt + 4))
#define BSZ (BKt * (BN + 4))

__global__ __launch_bounds__(256) void gemm_pipe(
    const float* __restrict__ A, const float* __restrict__ Bt,
    const float* __restrict__ bias, float* __restrict__ C,
    int M, int N, int K)
{
    extern __shared__ float smg[];
    float* As = smg;
    float* Bs = smg + NSTG * ASZ;

    const int tid  = threadIdx.x;
    const int lane = tid & 31;
    const int warp = tid >> 5;
    const int wm = warp & 3;
    const int wn = warp >> 2;
    const int bm = blockIdx.y, bn = blockIdx.x;
    const int g  = lane >> 2;
    const int tg = lane & 3;

    const float* Ag = A + (size_t)bm * BM * K;
    const float* Bg = Bt + (size_t)bn * BN;

    int arow[4], akc[4];
#pragma unroll
    for (int i = 0; i < 4; i++) {
        int f4 = tid + i * 256;
        arow[i] = f4 >> 3;
        akc[i]  = (f4 & 7) << 2;
    }
    int brow[2], bnc[2];
#pragma unroll
    for (int i = 0; i < 2; i++) {
        int f4 = tid + i * 256;
        brow[i] = f4 >> 4;
        bnc[i]  = (f4 & 15) << 2;
    }

    float acc[2][4][4];
#pragma unroll
    for (int i = 0; i < 2; i++)
#pragma unroll
        for (int j = 0; j < 4; j++)
#pragma unroll
            for (int r = 0; r < 4; r++) acc[i][j][r] = 0.f;

    const int T = K / BKt;

    auto issue = [&](int t, int buf) {
#pragma unroll
        for (int i = 0; i < 4; i++) {
            unsigned dst = sm_u32(&As[buf * ASZ + arow[i] * (BKt + 4) + akc[i]]);
            const float* src = Ag + (size_t)arow[i] * K + t * BKt + akc[i];
            asm volatile("cp.async.cg.shared.global [%0], [%1], 16;"
                         :: "r"(dst), "l"(src));
        }
#pragma unroll
        for (int i = 0; i < 2; i++) {
            unsigned dst = sm_u32(&Bs[buf * BSZ + brow[i] * (BN + 4) + bnc[i]]);
            const float* src = Bg + (size_t)(t * BKt + brow[i]) * N + bnc[i];
            asm volatile("cp.async.cg.shared.global [%0], [%1], 16;"
                         :: "r"(dst), "l"(src));
        }
        asm volatile("cp.async.commit_group;");
    };

    issue(0, 0);
    issue(1, 1);

    for (int t = 0; t < T; t++) {
        asm volatile("cp.async.wait_group 1;");
        __syncthreads();

        if (t + 2 < T) issue(t + 2, (t + 2) % NSTG);
        else asm volatile("cp.async.commit_group;");

        const int buf = t % NSTG;
        const float* Ab = As + buf * ASZ;
        const float* Bb = Bs + buf * BSZ;

#pragma unroll
        for (int ks = 0; ks < 4; ks++) {
            const int k0 = ks * 8;
            unsigned a[2][4], b[4][2];
#pragma unroll
            for (int mi = 0; mi < 2; mi++) {
                int m0 = wm * 32 + mi * 16;
                a[mi][0] = f2tf(Ab[(m0 + g    ) * (BKt + 4) + k0 + tg    ]);
                a[mi][1] = f2tf(Ab[(m0 + g + 8) * (BKt + 4) + k0 + tg    ]);
                a[mi][2] = f2tf(Ab[(m0 + g    ) * (BKt + 4) + k0 + tg + 4]);
                a[mi][3] = f2tf(Ab[(m0 + g + 8) * (BKt + 4) + k0 + tg + 4]);
            }
#pragma unroll
            for (int ni = 0; ni < 4; ni++) {
                int n0 = wn * 32 + ni * 8;
                b[ni][0] = __float_as_uint(Bb[(k0 + tg    ) * (BN + 4) + n0 + g]);
                b[ni][1] = __float_as_uint(Bb[(k0 + tg + 4) * (BN + 4) + n0 + g]);
            }
#pragma unroll
            for (int mi = 0; mi < 2; mi++)
#pragma unroll
                for (int ni = 0; ni < 4; ni++)
                    mma_tf32(acc[mi][ni], a[mi], b[ni][0], b[ni][1]);
        }
        __syncthreads();
    }

#pragma unroll
    for (int mi = 0; mi < 2; mi++) {
        int r0 = bm * BM + wm * 32 + mi * 16 + g;
#pragma unroll
        for (int ni = 0; ni < 4; ni++) {
            int c0 = bn * BN + wn * 32 + ni * 8 + tg * 2;
            float b0 = bias[c0], b1 = bias[c0 + 1];
            *(float2*)(C + (size_t)r0 * N + c0) =
                make_float2(acc[mi][ni][0] + b0, acc[mi][ni][1] + b1);
            *(float2*)(C + (size_t)(r0 + 8) * N + c0) =
                make_float2(acc[mi][ni][2] + b0, acc[mi][ni][3] + b1);
        }
    }
}

// ======================================================================
// Recurrence (R16): bf16x2 3-term k16 mma — halves tensor instr + W LDS.
// Protocol/update identical to R13/R14 (proven correct, 847 us).
// ======================================================================
__device__ __forceinline__ float sigf(float x) { return 1.f / (1.f + expf(-x)); }

// stage one W slice as packed bf16 hi/lo pairs: [k2 0..255][col 0..15], stride 24
__device__ __forceinline__ void stage_w(const float* __restrict__ W, int nc0,
                                        unsigned* wHiP, unsigned* wLoP, int tid)
{
    for (int i = tid; i < 1024; i += 512) {
        int k2 = i >> 2, gate = i & 3;
        const float* r0 = W + (size_t)(2 * k2) * G4N_ + gate * 512 + nc0;
        float4 we = *(const float4*)r0;          // even k = 2*k2
        float4 wo = *(const float4*)(r0 + G4N_); // odd  k = 2*k2+1
        float e[4] = {we.x, we.y, we.z, we.w};
        float o[4] = {wo.x, wo.y, wo.z, wo.w};
        unsigned h[4], l[4];
#pragma unroll
        for (int j = 0; j < 4; j++) {
            float2 p = make_float2(e[j], o[j]);
            pack_hl(p, h[j], l[j]);
        }
        *(uint4*)&wHiP[k2 * WS2_ + gate * 4] = make_uint4(h[0], h[1], h[2], h[3]);
        *(uint4*)&wLoP[k2 * WS2_ + gate * 4] = make_uint4(l[0], l[1], l[2], l[3]);
    }
}

__global__ __launch_bounds__(512, 1) void recurrence(
    const float* __restrict__ Wenc,
    const float* __restrict__ Wdec,
    const float* __restrict__ xk,
    const float* __restrict__ lb,
    float* __restrict__ preds)
{
    extern __shared__ float sm[];
    unsigned* wHiP = (unsigned*)sm;            // 256*24 = 6144 u32
    unsigned* wLoP = (unsigned*)(sm + 6144);   // 6144 u32
    float* hsh     = sm + 12288;               // 32 x 516 = 16512 floats
    float* psumB   = sm + 28800;               // 2 x 4608 floats

    const int tid  = threadIdx.x;
    const int lane = tid & 31;
    const int warp = tid >> 5;
    const int g    = lane >> 2;
    const int tg   = lane & 3;
    const int kg   = warp & 7;
    const int mi   = warp >> 3;
    const int m0   = mi * 16;
    const int nc0  = blockIdx.x * 4;

    const unsigned base = g_flags[blockIdx.x * 32];

    stage_w(Wenc, nc0, wHiP, wLoP, tid);

    const int b  = tid & 31;
    const int cu = tid >> 5;
    float lbr[4], cst = 0.f, pf[4];
    if (tid < 128) {
        d_h[0][(size_t)b * N_ + nc0 + cu] = 0.f;
#pragma unroll
        for (int q = 0; q < 4; q++) lbr[q] = lb[q * 512 + nc0 + cu];
        const float* xp = xk + ((size_t)b * H_) * G4N_ + nc0 + cu;
        pf[0] = __ldg(xp);
        pf[1] = __ldg(xp + 512);
        pf[2] = __ldg(xp + 1024);
        pf[3] = __ldg(xp + 1536);
    }
    __syncthreads();
    if (tid == 0)
        asm volatile("st.release.gpu.global.u32 [%0], %1;"
                     :: "l"(&g_flags[blockIdx.x * 32]), "r"(base + 1u) : "memory");

    const int jj = kg * 16 + (lane & 15);
    const unsigned* flagp = &g_flags[jj * 32];
    const int half = lane >> 4;
    const int r0s  = m0 + half * 8;
    const int scol = kg * 64 + (lane & 15) * 4;

    for (int s = 0; s < H_ + P_; s++) {
        if (s == H_) {
            stage_w(Wdec, nc0, wHiP, wLoP, tid);
            __syncthreads();
        }

        float pfn[4];
        if (tid < 128) {
            if (s + 1 < H_) {
                const float* xp = xk + ((size_t)b * H_ + (s + 1)) * G4N_ + nc0 + cu;
                pfn[0] = __ldg(xp);
                pfn[1] = __ldg(xp + 512);
                pfn[2] = __ldg(xp + 1024);
                pfn[3] = __ldg(xp + 1536);
            } else {
                pfn[0] = lbr[0]; pfn[1] = lbr[1]; pfn[2] = lbr[2]; pfn[3] = lbr[3];
            }
        }

        {
            const unsigned tgt = base + 1u + (unsigned)s;
            unsigned v;
            do {
                asm volatile("ld.acquire.gpu.global.u32 %0, [%1];"
                             : "=r"(v) : "l"(flagp) : "memory");
            } while ((int)(v - tgt) < 0);
        }
        {
            const float4* hb = (const float4*)d_h[s & 1];
            float4 hv[8];
#pragma unroll
            for (int r = 0; r < 8; r++)
                hv[r] = __ldcg(hb + (size_t)(r0s + r) * 128 + jj);
#pragma unroll
            for (int r = 0; r < 8; r++)
                *(float4*)&hsh[(r0s + r) * HS_ + scol] = hv[r];
        }
        __syncwarp();

        // ---- bf16x2 3-term mma: rows [m0,m0+16), k-slice [kg*64,+64) ----
        float ac0[2][4] = {{0.f,0.f,0.f,0.f},{0.f,0.f,0.f,0.f}};
        float ac1[2][4] = {{0.f,0.f,0.f,0.f},{0.f,0.f,0.f,0.f}};
#pragma unroll
        for (int f2 = 0; f2 < 4; f2++) {
            const int K0 = kg * 64 + f2 * 16;
            const int c = f2 & 1;
            // A: h fp32 pairs -> bf16 hi/lo packed
            float2 p00 = *(const float2*)&hsh[(m0 + g    ) * HS_ + K0 + 2 * tg    ];
            float2 p10 = *(const float2*)&hsh[(m0 + g + 8) * HS_ + K0 + 2 * tg    ];
            float2 p01 = *(const float2*)&hsh[(m0 + g    ) * HS_ + K0 + 2 * tg + 8];
            float2 p11 = *(const float2*)&hsh[(m0 + g + 8) * HS_ + K0 + 2 * tg + 8];
            unsigned ahi[4], alo[4];
            pack_hl(p00, ahi[0], alo[0]);
            pack_hl(p10, ahi[1], alo[1]);
            pack_hl(p01, ahi[2], alo[2]);
            pack_hl(p11, ahi[3], alo[3]);
            // B frags (packed pairs precomputed)
            const int kb = kg * 32 + f2 * 8;
            unsigned bh0 = wHiP[(kb + tg    ) * WS2_ + g];
            unsigned bh1 = wHiP[(kb + tg + 4) * WS2_ + g];
            unsigned bh2 = wHiP[(kb + tg    ) * WS2_ + 8 + g];
            unsigned bh3 = wHiP[(kb + tg + 4) * WS2_ + 8 + g];
            unsigned bl0 = wLoP[(kb + tg    ) * WS2_ + g];
            unsigned bl1 = wLoP[(kb + tg + 4) * WS2_ + g];
            unsigned bl2 = wLoP[(kb + tg    ) * WS2_ + 8 + g];
            unsigned bl3 = wLoP[(kb + tg + 4) * WS2_ + 8 + g];
            mma_bf16(ac0[c], ahi, bh0, bh1);
            mma_bf16(ac0[c], alo, bh0, bh1);
            mma_bf16(ac0[c], ahi, bl0, bl1);
            mma_bf16(ac1[c], ahi, bh2, bh3);
            mma_bf16(ac1[c], alo, bh2, bh3);
            mma_bf16(ac1[c], ahi, bl2, bl3);
        }
        {
            float* psum = psumB + (s & 1) * 4608;
            const int c0 = tg * 2, r0 = m0 + g;
            psum[(kg * 16 + c0        ) * PS_ + r0    ] = ac0[0][0] + ac0[1][0];
            psum[(kg * 16 + c0 + 1    ) * PS_ + r0    ] = ac0[0][1] + ac0[1][1];
            psum[(kg * 16 + c0        ) * PS_ + r0 + 8] = ac0[0][2] + ac0[1][2];
            psum[(kg * 16 + c0 + 1    ) * PS_ + r0 + 8] = ac0[0][3] + ac0[1][3];
            psum[(kg * 16 + 8 + c0    ) * PS_ + r0    ] = ac1[0][0] + ac1[1][0];
            psum[(kg * 16 + 8 + c0 + 1) * PS_ + r0    ] = ac1[0][1] + ac1[1][1];
            psum[(kg * 16 + 8 + c0    ) * PS_ + r0 + 8] = ac1[0][2] + ac1[1][2];
            psum[(kg * 16 + 8 + c0 + 1) * PS_ + r0 + 8] = ac1[0][3] + ac1[1][3];
        }
        __syncthreads();

        if (tid < 128) {
            const float* psum = psumB + (s & 1) * 4608;
            float z[4];
#pragma unroll
            for (int q = 0; q < 4; q++) {
                const int n = q * 4 + cu;
                float accv = pf[q];
#pragma unroll
                for (int kk = 0; kk < 8; kk++)
                    accv += psum[(kk * 16 + n) * PS_ + b];
                z[q] = accv;
            }
            float ii = sigf(z[0]), ff = sigf(z[1]);
            float gg = tanhf(z[2]), oo = sigf(z[3]);
            cst = ff * cst + ii * gg;
            float hn = oo * tanhf(cst);
            d_h[(s + 1) & 1][(size_t)b * N_ + nc0 + cu] = hn;

            asm volatile("bar.sync 1, 128;" ::: "memory");
            if (tid == 0)
                asm volatile("st.release.gpu.global.u32 [%0], %1;"
                             :: "l"(&g_flags[blockIdx.x * 32]),
                                "r"(base + 2u + (unsigned)s) : "memory");

            if (s >= H_)
                preds[((size_t)b * P_ + (s - H_)) * N_ + nc0 + cu] = hn;

            pf[0] = pfn[0]; pf[1] = pfn[1]; pf[2] = pfn[2]; pf[3] = pfn[3];
        }
    }
}

// ======================================================================
// launch
// ======================================================================
extern "C" void kernel_launch(void* const* d_in, const int* in_sizes, int n_in,
                              void* d_out, int out_size)
{
    const float* x       = (const float*)d_in[0];
    const float* conv_w  = (const float*)d_in[1];
    const float* conv_b  = (const float*)d_in[2];
    const float* lstm_k  = (const float*)d_in[3];
    const float* lstm_rk = (const float*)d_in[4];
    const float* lstm_b  = (const float*)d_in[5];
    const float* dense_w = (const float*)d_in[6];
    const float* dense_b = (const float*)d_in[7];
    float* out = (float*)d_out;

    float *xr, *xk, *wdec, *preds, *cw, *lk, *dw;
    cudaGetSymbolAddress((void**)&xr,    d_xr);
    cudaGetSymbolAddress((void**)&xk,    d_xk);
    cudaGetSymbolAddress((void**)&wdec,  d_wdec);
    cudaGetSymbolAddress((void**)&preds, d_preds);
    cudaGetSymbolAddress((void**)&cw,    d_cw);
    cudaGetSymbolAddress((void**)&lk,    d_lk);
    cudaGetSymbolAddress((void**)&dw,    d_dw);

    const int GSMEM = NSTG * (ASZ + BSZ) * 4;  // 81408 B
    cudaFuncSetAttribute(gemm_pipe, cudaFuncAttributeMaxDynamicSharedMemorySize, GSMEM);
    const int RSMEM = (6144 + 6144 + 16512 + 2 * 4608) * 4;  // 152064 B
    cudaFuncSetAttribute(recurrence, cudaFuncAttributeMaxDynamicSharedMemorySize, RSMEM);

    // 0) weight prep
    prep<<<(KIN_ * N_ + 255) / 256, 256>>>(conv_w, lstm_k, lstm_rk, dense_w);

    // 1) xr = reshape(x) @ conv_w + conv_b
    {
        dim3 grid(N_ / BN, MR_ / BM);
        gemm_pipe<<<grid, 256, GSMEM>>>(x, cw, conv_b, xr, MR_, N_, KIN_);
    }
    // 2) xk = xr @ lstm_k + lstm_b
    {
        dim3 grid(G4N_ / BN, MR_ / BM);
        gemm_pipe<<<grid, 256, GSMEM>>>(xr, lk, lstm_b, xk, MR_, G4N_, N_);
    }
    // 3) recurrence (persistent dataflow)
    recurrence<<<RGRID, 512, RSMEM>>>(lstm_rk, wdec, xk, lstm_b, preds);
    // 4) out = preds @ dense_w + dense_b
    {
        dim3 grid(N_ / BN, (B_ * P_) / BM);
        gemm_pipe<<<grid, 256, GSMEM>>>(preds, dw, dense_b, out, B_ * P_, N_, N_);
    }
}

// round 17
// speedup vs baseline: 1.1611x; 1.0504x over previous
#include <cuda_runtime.h>
#include <cstdint>

// ---------------- problem constants ----------------
#define B_   32
#define H_   168
#define N_   512
#define F_   8
#define P_   24
#define KIN_ (N_ * F_)   // 4096
#define G4N_ (4 * N_)    // 2048
#define MR_  (B_ * H_)   // 5376
#define RGRID 128
#define WS2_ 24          // packed-W row stride (conflict-free B-frag LDS)
#define HS2_ 260         // packed-h row stride in u32 (260 % 32 == 4)
#define PS_  36          // psum b-stride

typedef unsigned long long ull;

// ---------------- device scratch ----------------
__device__ float d_xr[(size_t)MR_ * N_];
__device__ float d_xk[(size_t)MR_ * G4N_];
__device__ float d_wdec[(size_t)N_ * G4N_];
__device__ float d_cw[(size_t)KIN_ * N_];
__device__ float d_lk[(size_t)N_ * G4N_];
__device__ float d_dw[(size_t)N_ * N_];
__device__ float d_h[2][B_ * N_];
__device__ float d_preds[(size_t)B_ * P_ * N_];
__device__ unsigned g_flags[RGRID * 32];

// ---------------- helpers ----------------
__device__ __forceinline__ unsigned f2tf(float x) {
    unsigned r;
    asm("cvt.rna.tf32.f32 %0, %1;" : "=r"(r) : "f"(x));
    return r;
}

__device__ __forceinline__ void mma_tf32(float* c, const unsigned* a,
                                         unsigned b0, unsigned b1) {
    asm volatile(
        "mma.sync.aligned.m16n8k8.row.col.f32.tf32.tf32.f32 "
        "{%0,%1,%2,%3},{%4,%5,%6,%7},{%8,%9},{%0,%1,%2,%3};"
        : "+f"(c[0]), "+f"(c[1]), "+f"(c[2]), "+f"(c[3])
        : "r"(a[0]), "r"(a[1]), "r"(a[2]), "r"(a[3]), "r"(b0), "r"(b1));
}

__device__ __forceinline__ void mma_bf16(float* c, const unsigned* a,
                                         unsigned b0, unsigned b1) {
    asm volatile(
        "mma.sync.aligned.m16n8k16.row.col.f32.bf16.bf16.f32 "
        "{%0,%1,%2,%3},{%4,%5,%6,%7},{%8,%9},{%0,%1,%2,%3};"
        : "+f"(c[0]), "+f"(c[1]), "+f"(c[2]), "+f"(c[3])
        : "r"(a[0]), "r"(a[1]), "r"(a[2]), "r"(a[3]), "r"(b0), "r"(b1));
}

// pack float2 (even=x, odd=y) -> bf16x2 hi word + bf16x2 lo-residual word
__device__ __forceinline__ void pack_hl(float2 p, unsigned& hi, unsigned& lo) {
    asm("cvt.rn.bf16x2.f32 %0, %1, %2;" : "=r"(hi) : "f"(p.y), "f"(p.x));
    float eh = __uint_as_float(hi << 16);
    float oh = __uint_as_float(hi & 0xFFFF0000u);
    float el = p.x - eh, ol = p.y - oh;
    asm("cvt.rn.bf16x2.f32 %0, %1, %2;" : "=r"(lo) : "f"(ol), "f"(el));
}

__device__ __forceinline__ unsigned sm_u32(const void* p) {
    return (unsigned)__cvta_generic_to_shared(p);
}

// ======================================================================
// prep
// ======================================================================
__global__ void prep(const float* __restrict__ cw, const float* __restrict__ lk,
                     const float* __restrict__ rk, const float* __restrict__ dw)
{
    int i = blockIdx.x * blockDim.x + threadIdx.x;
    if (i < KIN_ * N_) d_cw[i] = __uint_as_float(f2tf(cw[i]));
    if (i < N_ * G4N_) {
        d_lk[i]   = __uint_as_float(f2tf(lk[i]));
        d_wdec[i] = lk[i] + rk[i];
    }
    if (i < N_ * N_) d_dw[i] = __uint_as_float(f2tf(dw[i]));
}

// ======================================================================
// GEMM — exact R14 config (best measured): 128x64 tile, cp.async 3-stage
// ======================================================================
#define BM 128
#define BN 64
#define BKt 32
#define NSTG 3
#define ASZ (BM * (BKt + 4))
#define BSZ (BKt * (BN + 4))

__global__ __launch_bounds__(256) void gemm_pipe(
    const float* __restrict__ A, const float* __restrict__ Bt,
    const float* __restrict__ bias, float* __restrict__ C,
    int M, int N, int K)
{
    extern __shared__ float smg[];
    float* As = smg;
    float* Bs = smg + NSTG * ASZ;

    const int tid  = threadIdx.x;
    const int lane = tid & 31;
    const int warp = tid >> 5;
    const int wm = warp & 3;
    const int wn = warp >> 2;
    const int bm = blockIdx.y, bn = blockIdx.x;
    const int g  = lane >> 2;
    const int tg = lane & 3;

    const float* Ag = A + (size_t)bm * BM * K;
    const float* Bg = Bt + (size_t)bn * BN;

    int arow[4], akc[4];
#pragma unroll
    for (int i = 0; i < 4; i++) {
        int f4 = tid + i * 256;
        arow[i] = f4 >> 3;
        akc[i]  = (f4 & 7) << 2;
    }
    int brow[2], bnc[2];
#pragma unroll
    for (int i = 0; i < 2; i++) {
        int f4 = tid + i * 256;
        brow[i] = f4 >> 4;
        bnc[i]  = (f4 & 15) << 2;
    }

    float acc[2][4][4];
#pragma unroll
    for (int i = 0; i < 2; i++)
#pragma unroll
        for (int j = 0; j < 4; j++)
#pragma unroll
            for (int r = 0; r < 4; r++) acc[i][j][r] = 0.f;

    const int T = K / BKt;

    auto issue = [&](int t, int buf) {
#pragma unroll
        for (int i = 0; i < 4; i++) {
            unsigned dst = sm_u32(&As[buf * ASZ + arow[i] * (BKt + 4) + akc[i]]);
            const float* src = Ag + (size_t)arow[i] * K + t * BKt + akc[i];
            asm volatile("cp.async.cg.shared.global [%0], [%1], 16;"
                         :: "r"(dst), "l"(src));
        }
#pragma unroll
        for (int i = 0; i < 2; i++) {
            unsigned dst = sm_u32(&Bs[buf * BSZ + brow[i] * (BN + 4) + bnc[i]]);
            const float* src = Bg + (size_t)(t * BKt + brow[i]) * N + bnc[i];
            asm volatile("cp.async.cg.shared.global [%0], [%1], 16;"
                         :: "r"(dst), "l"(src));
        }
        asm volatile("cp.async.commit_group;");
    };

    issue(0, 0);
    issue(1, 1);

    for (int t = 0; t < T; t++) {
        asm volatile("cp.async.wait_group 1;");
        __syncthreads();

        if (t + 2 < T) issue(t + 2, (t + 2) % NSTG);
        else asm volatile("cp.async.commit_group;");

        const int buf = t % NSTG;
        const float* Ab = As + buf * ASZ;
        const float* Bb = Bs + buf * BSZ;

#pragma unroll
        for (int ks = 0; ks < 4; ks++) {
            const int k0 = ks * 8;
            unsigned a[2][4], b[4][2];
#pragma unroll
            for (int mi = 0; mi < 2; mi++) {
                int m0 = wm * 32 + mi * 16;
                a[mi][0] = f2tf(Ab[(m0 + g    ) * (BKt + 4) + k0 + tg    ]);
                a[mi][1] = f2tf(Ab[(m0 + g + 8) * (BKt + 4) + k0 + tg    ]);
                a[mi][2] = f2tf(Ab[(m0 + g    ) * (BKt + 4) + k0 + tg + 4]);
                a[mi][3] = f2tf(Ab[(m0 + g + 8) * (BKt + 4) + k0 + tg + 4]);
            }
#pragma unroll
            for (int ni = 0; ni < 4; ni++) {
                int n0 = wn * 32 + ni * 8;
                b[ni][0] = __float_as_uint(Bb[(k0 + tg    ) * (BN + 4) + n0 + g]);
                b[ni][1] = __float_as_uint(Bb[(k0 + tg + 4) * (BN + 4) + n0 + g]);
            }
#pragma unroll
            for (int mi = 0; mi < 2; mi++)
#pragma unroll
                for (int ni = 0; ni < 4; ni++)
                    mma_tf32(acc[mi][ni], a[mi], b[ni][0], b[ni][1]);
        }
        __syncthreads();
    }

#pragma unroll
    for (int mi = 0; mi < 2; mi++) {
        int r0 = bm * BM + wm * 32 + mi * 16 + g;
#pragma unroll
        for (int ni = 0; ni < 4; ni++) {
            int c0 = bn * BN + wn * 32 + ni * 8 + tg * 2;
            float b0 = bias[c0], b1 = bias[c0 + 1];
            *(float2*)(C + (size_t)r0 * N + c0) =
                make_float2(acc[mi][ni][0] + b0, acc[mi][ni][1] + b1);
            *(float2*)(C + (size_t)(r0 + 8) * N + c0) =
                make_float2(acc[mi][ni][2] + b0, acc[mi][ni][3] + b1);
        }
    }
}

// ======================================================================
// Recurrence (R17): h packed to bf16 hi/lo DURING STAGING (pack ALU hides
// under the __ldcg latency); mma loop is pure LDS.32 + mma.
// Protocol identical to R16 (682 us).
// ======================================================================
__device__ __forceinline__ float sigf(float x) { return 1.f / (1.f + expf(-x)); }

// stage one W slice as packed bf16 hi/lo pairs: [k2 0..255][col 0..15], stride 24
__device__ __forceinline__ void stage_w(const float* __restrict__ W, int nc0,
                                        unsigned* wHiP, unsigned* wLoP, int tid)
{
    for (int i = tid; i < 1024; i += 512) {
        int k2 = i >> 2, gate = i & 3;
        const float* r0 = W + (size_t)(2 * k2) * G4N_ + gate * 512 + nc0;
        float4 we = *(const float4*)r0;
        float4 wo = *(const float4*)(r0 + G4N_);
        float e[4] = {we.x, we.y, we.z, we.w};
        float o[4] = {wo.x, wo.y, wo.z, wo.w};
        unsigned h[4], l[4];
#pragma unroll
        for (int j = 0; j < 4; j++) {
            float2 p = make_float2(e[j], o[j]);
            pack_hl(p, h[j], l[j]);
        }
        *(uint4*)&wHiP[k2 * WS2_ + gate * 4] = make_uint4(h[0], h[1], h[2], h[3]);
        *(uint4*)&wLoP[k2 * WS2_ + gate * 4] = make_uint4(l[0], l[1], l[2], l[3]);
    }
}

__global__ __launch_bounds__(512, 1) void recurrence(
    const float* __restrict__ Wenc,
    const float* __restrict__ Wdec,
    const float* __restrict__ xk,
    const float* __restrict__ lb,
    float* __restrict__ preds)
{
    extern __shared__ float sm[];
    unsigned* wHiP = (unsigned*)sm;             // 6144 u32
    unsigned* wLoP = (unsigned*)(sm + 6144);    // 6144 u32
    unsigned* hiA  = (unsigned*)(sm + 12288);   // 32 x 260 = 8320 u32
    unsigned* loA  = (unsigned*)(sm + 20608);   // 8320 u32
    float* psumB   = sm + 28928;                // 2 x 4608 floats

    const int tid  = threadIdx.x;
    const int lane = tid & 31;
    const int warp = tid >> 5;
    const int g    = lane >> 2;
    const int tg   = lane & 3;
    const int kg   = warp & 7;
    const int mi   = warp >> 3;
    const int m0   = mi * 16;
    const int nc0  = blockIdx.x * 4;

    const unsigned base = g_flags[blockIdx.x * 32];

    stage_w(Wenc, nc0, wHiP, wLoP, tid);

    const int b  = tid & 31;
    const int cu = tid >> 5;
    float lbr[4], cst = 0.f, pf[4];
    if (tid < 128) {
        d_h[0][(size_t)b * N_ + nc0 + cu] = 0.f;
#pragma unroll
        for (int q = 0; q < 4; q++) lbr[q] = lb[q * 512 + nc0 + cu];
        const float* xp = xk + ((size_t)b * H_) * G4N_ + nc0 + cu;
        pf[0] = __ldg(xp);
        pf[1] = __ldg(xp + 512);
        pf[2] = __ldg(xp + 1024);
        pf[3] = __ldg(xp + 1536);
    }
    __syncthreads();
    if (tid == 0)
        asm volatile("st.release.gpu.global.u32 [%0], %1;"
                     :: "l"(&g_flags[blockIdx.x * 32]), "r"(base + 1u) : "memory");

    const int jj = kg * 16 + (lane & 15);
    const unsigned* flagp = &g_flags[jj * 32];
    const int half = lane >> 4;
    const int r0s  = m0 + half * 8;

    for (int s = 0; s < H_ + P_; s++) {
        if (s == H_) {
            stage_w(Wdec, nc0, wHiP, wLoP, tid);
            __syncthreads();
        }

        float pfn[4];
        if (tid < 128) {
            if (s + 1 < H_) {
                const float* xp = xk + ((size_t)b * H_ + (s + 1)) * G4N_ + nc0 + cu;
                pfn[0] = __ldg(xp);
                pfn[1] = __ldg(xp + 512);
                pfn[2] = __ldg(xp + 1024);
                pfn[3] = __ldg(xp + 1536);
            } else {
                pfn[0] = lbr[0]; pfn[1] = lbr[1]; pfn[2] = lbr[2]; pfn[3] = lbr[3];
            }
        }

        // ---- wait for producer jj ----
        {
            const unsigned tgt = base + 1u + (unsigned)s;
            unsigned v;
            do {
                asm volatile("ld.acquire.gpu.global.u32 %0, [%1];"
                             : "=r"(v) : "l"(flagp) : "memory");
            } while ((int)(v - tgt) < 0);
        }
        // ---- stage + PACK producer jj's h slice (pack hides under LDG) ----
        {
            const float4* hb = (const float4*)d_h[s & 1];
            float4 hv[8];
#pragma unroll
            for (int r = 0; r < 8; r++)
                hv[r] = __ldcg(hb + (size_t)(r0s + r) * 128 + jj);
#pragma unroll
            for (int r = 0; r < 8; r++) {
                unsigned h0, l0, h1, l1;
                pack_hl(make_float2(hv[r].x, hv[r].y), h0, l0);
                pack_hl(make_float2(hv[r].z, hv[r].w), h1, l1);
                const int off = (r0s + r) * HS2_ + 2 * jj;
                *(uint2*)&hiA[off] = make_uint2(h0, h1);
                *(uint2*)&loA[off] = make_uint2(l0, l1);
            }
        }
        __syncwarp();

        // ---- bf16x2 3-term mma: pure LDS + mma (no pack ALU) ----
        float ac0[2][4] = {{0.f,0.f,0.f,0.f},{0.f,0.f,0.f,0.f}};
        float ac1[2][4] = {{0.f,0.f,0.f,0.f},{0.f,0.f,0.f,0.f}};
#pragma unroll
        for (int f2 = 0; f2 < 4; f2++) {
            const int c = f2 & 1;
            const int kb2 = kg * 32 + f2 * 8;    // k2 base for A
            unsigned ahi[4], alo[4];
            ahi[0] = hiA[(m0 + g    ) * HS2_ + kb2 + tg    ];
            ahi[1] = hiA[(m0 + g + 8) * HS2_ + kb2 + tg    ];
            ahi[2] = hiA[(m0 + g    ) * HS2_ + kb2 + tg + 4];
            ahi[3] = hiA[(m0 + g + 8) * HS2_ + kb2 + tg + 4];
            alo[0] = loA[(m0 + g    ) * HS2_ + kb2 + tg    ];
            alo[1] = loA[(m0 + g + 8) * HS2_ + kb2 + tg    ];
            alo[2] = loA[(m0 + g    ) * HS2_ + kb2 + tg + 4];
            alo[3] = loA[(m0 + g + 8) * HS2_ + kb2 + tg + 4];
            const int kb = kg * 32 + f2 * 8;     // k2 base for B (same)
            unsigned bh0 = wHiP[(kb + tg    ) * WS2_ + g];
            unsigned bh1 = wHiP[(kb + tg + 4) * WS2_ + g];
            unsigned bh2 = wHiP[(kb + tg    ) * WS2_ + 8 + g];
            unsigned bh3 = wHiP[(kb + tg + 4) * WS2_ + 8 + g];
            unsigned bl0 = wLoP[(kb + tg    ) * WS2_ + g];
            unsigned bl1 = wLoP[(kb + tg + 4) * WS2_ + g];
            unsigned bl2 = wLoP[(kb + tg    ) * WS2_ + 8 + g];
            unsigned bl3 = wLoP[(kb + tg + 4) * WS2_ + 8 + g];
            mma_bf16(ac0[c], ahi, bh0, bh1);
            mma_bf16(ac0[c], alo, bh0, bh1);
            mma_bf16(ac0[c], ahi, bl0, bl1);
            mma_bf16(ac1[c], ahi, bh2, bh3);
            mma_bf16(ac1[c], alo, bh2, bh3);
            mma_bf16(ac1[c], ahi, bl2, bl3);
        }
        {
            float* psum = psumB + (s & 1) * 4608;
            const int c0 = tg * 2, r0 = m0 + g;
            psum[(kg * 16 + c0        ) * PS_ + r0    ] = ac0[0][0] + ac0[1][0];
            psum[(kg * 16 + c0 + 1    ) * PS_ + r0    ] = ac0[0][1] + ac0[1][1];
            psum[(kg * 16 + c0        ) * PS_ + r0 + 8] = ac0[0][2] + ac0[1][2];
            psum[(kg * 16 + c0 + 1    ) * PS_ + r0 + 8] = ac0[0][3] + ac0[1][3];
            psum[(kg * 16 + 8 + c0    ) * PS_ + r0    ] = ac1[0][0] + ac1[1][0];
            psum[(kg * 16 + 8 + c0 + 1) * PS_ + r0    ] = ac1[0][1] + ac1[1][1];
            psum[(kg * 16 + 8 + c0    ) * PS_ + r0 + 8] = ac1[0][2] + ac1[1][2];
            psum[(kg * 16 + 8 + c0 + 1) * PS_ + r0 + 8] = ac1[0][3] + ac1[1][3];
        }
        __syncthreads();

        if (tid < 128) {
            const float* psum = psumB + (s & 1) * 4608;
            float z[4];
#pragma unroll
            for (int q = 0; q < 4; q++) {
                const int n = q * 4 + cu;
                float accv = pf[q];
#pragma unroll
                for (int kk = 0; kk < 8; kk++)
                    accv += psum[(kk * 16 + n) * PS_ + b];
                z[q] = accv;
            }
            float ii = sigf(z[0]), ff = sigf(z[1]);
            float gg = tanhf(z[2]), oo = sigf(z[3]);
            cst = ff * cst + ii * gg;
            float hn = oo * tanhf(cst);
            d_h[(s + 1) & 1][(size_t)b * N_ + nc0 + cu] = hn;

            asm volatile("bar.sync 1, 128;" ::: "memory");
            if (tid == 0)
                asm volatile("st.release.gpu.global.u32 [%0], %1;"
                             :: "l"(&g_flags[blockIdx.x * 32]),
                                "r"(base + 2u + (unsigned)s) : "memory");

            if (s >= H_)
                preds[((size_t)b * P_ + (s - H_)) * N_ + nc0 + cu] = hn;

            pf[0] = pfn[0]; pf[1] = pfn[1]; pf[2] = pfn[2]; pf[3] = pfn[3];
        }
    }
}

// ======================================================================
// launch
// ======================================================================
extern "C" void kernel_launch(void* const* d_in, const int* in_sizes, int n_in,
                              void* d_out, int out_size)
{
    const float* x       = (const float*)d_in[0];
    const float* conv_w  = (const float*)d_in[1];
    const float* conv_b  = (const float*)d_in[2];
    const float* lstm_k  = (const float*)d_in[3];
    const float* lstm_rk = (const float*)d_in[4];
    const float* lstm_b  = (const float*)d_in[5];
    const float* dense_w = (const float*)d_in[6];
    const float* dense_b = (const float*)d_in[7];
    float* out = (float*)d_out;

    float *xr, *xk, *wdec, *preds, *cw, *lk, *dw;
    cudaGetSymbolAddress((void**)&xr,    d_xr);
    cudaGetSymbolAddress((void**)&xk,    d_xk);
    cudaGetSymbolAddress((void**)&wdec,  d_wdec);
    cudaGetSymbolAddress((void**)&preds, d_preds);
    cudaGetSymbolAddress((void**)&cw,    d_cw);
    cudaGetSymbolAddress((void**)&lk,    d_lk);
    cudaGetSymbolAddress((void**)&dw,    d_dw);

    const int GSMEM = NSTG * (ASZ + BSZ) * 4;  // 81408 B
    cudaFuncSetAttribute(gemm_pipe, cudaFuncAttributeMaxDynamicSharedMemorySize, GSMEM);
    const int RSMEM = (6144 + 6144 + 8320 + 8320 + 2 * 4608) * 4;  // 152576 B
    cudaFuncSetAttribute(recurrence, cudaFuncAttributeMaxDynamicSharedMemorySize, RSMEM);

    // 0) weight prep
    prep<<<(KIN_ * N_ + 255) / 256, 256>>>(conv_w, lstm_k, lstm_rk, dense_w);

    // 1) xr = reshape(x) @ conv_w + conv_b
    {
        dim3 grid(N_ / BN, MR_ / BM);
        gemm_pipe<<<grid, 256, GSMEM>>>(x, cw, conv_b, xr, MR_, N_, KIN_);
    }
    // 2) xk = xr @ lstm_k + lstm_b
    {
        dim3 grid(G4N_ / BN, MR_ / BM);
        gemm_pipe<<<grid, 256, GSMEM>>>(xr, lk, lstm_b, xk, MR_, G4N_, N_);
    }
    // 3) recurrence (persistent dataflow)
    recurrence<<<RGRID, 512, RSMEM>>>(lstm_rk, wdec, xk, lstm_b, preds);
    // 4) out = preds @ dense_w + dense_b
    {
        dim3 grid(N_ / BN, (B_ * P_) / BM);
        gemm_pipe<<<grid, 256, GSMEM>>>(preds, dw, dense_b, out, B_ * P_, N_, N_);
    }
}